// round 15
// baseline (speedup 1.0000x reference)
#include <cuda_runtime.h>
#include <cstdint>

// Problem dims (fixed)
#define B_  16
#define U_  64
#define T_  128
#define E_  128
#define HID_ 256
#define H_  4
#define ENC_H_ 128
#define IN_DIM_ 32

typedef unsigned long long ull;

// Scratch (device globals: no allocation allowed)
__device__ float g_qu[B_ * U_ * HID_];    // ue @ fw1[:E]          (1024 x 256)
__device__ float g_kh[B_ * T_ * HID_];    // te @ fw1[E:]          (2048 x 256)
__device__ float g_qb[H_ * HID_];         // head_q @ fw1[:E] + fb1 (4 x 256)
__device__ float g_part[2][B_ * H_ * U_ * T_];  // d-half partial sums

// k-quad packed weights: Wq[k4][c] = float4(W[4k4][c], W[4k4+1][c], W[4k4+2][c], W[4k4+3][c])
#define QW0_OFF 0
#define QW1_OFF 4096
#define QW2_OFF 20480
#define QT0_OFF 36864
#define QT1_OFF 40960
#define QT2_OFF 57344
#define QF1_OFF 73728
#define WPACK_TOTAL 139264
__device__ float g_wpack[WPACK_TOTAL];

// ---- packed f32x2 helpers (Blackwell) ----
__device__ __forceinline__ ull add2(ull a, ull b) {
    ull r;
    asm("add.rn.f32x2 %0, %1, %2;" : "=l"(r) : "l"(a), "l"(b));
    return r;
}
__device__ __forceinline__ void fma2(ull& acc, ull a, ull b) {
    asm("fma.rn.f32x2 %0, %1, %2, %0;" : "+l"(acc) : "l"(a), "l"(b));
}
__device__ __forceinline__ ull relu2(ull x) {
    float lo, hi;
    asm("mov.b64 {%0,%1}, %2;" : "=f"(lo), "=f"(hi) : "l"(x));
    lo = fmaxf(lo, 0.f);
    hi = fmaxf(hi, 0.f);
    ull r;
    asm("mov.b64 %0, {%1,%2};" : "=l"(r) : "f"(lo), "f"(hi));
    return r;
}
__device__ __forceinline__ float hsum2(ull x) {
    float lo, hi;
    asm("mov.b64 {%0,%1}, %2;" : "=f"(lo), "=f"(hi) : "l"(x));
    return lo + hi;
}

// ---------------------------------------------------------------------------
// Pack kernel: k-quad interleave every weight matrix.  Segment table (blocks
// of 256 quads):
//  [0,4) uw0 | [4,20) uw1 | [20,36) uw2 | [36,40) tw0 | [40,56) tw1
//  [56,72) tw2 | [72,136) fw1
// ---------------------------------------------------------------------------
__global__ __launch_bounds__(256) void pack4_kernel(
    const float* __restrict__ uw0, const float* __restrict__ uw1,
    const float* __restrict__ uw2, const float* __restrict__ tw0,
    const float* __restrict__ tw1, const float* __restrict__ tw2,
    const float* __restrict__ fw1)
{
    const int b = blockIdx.x;
    const int t = threadIdx.x;
    const float* src;
    int C, dstoff, quad0;
    if      (b < 4)   { src = uw0; C = 128; dstoff = QW0_OFF; quad0 = b * 256; }
    else if (b < 20)  { src = uw1; C = 128; dstoff = QW1_OFF; quad0 = (b - 4) * 256; }
    else if (b < 36)  { src = uw2; C = 128; dstoff = QW2_OFF; quad0 = (b - 20) * 256; }
    else if (b < 40)  { src = tw0; C = 128; dstoff = QT0_OFF; quad0 = (b - 36) * 256; }
    else if (b < 56)  { src = tw1; C = 128; dstoff = QT1_OFF; quad0 = (b - 40) * 256; }
    else if (b < 72)  { src = tw2; C = 128; dstoff = QT2_OFF; quad0 = (b - 56) * 256; }
    else              { src = fw1; C = 256; dstoff = QF1_OFF; quad0 = (b - 72) * 256; }

    int p  = quad0 + t;
    int k4 = (C == 128) ? (p >> 7) : (p >> 8);
    int c  = (C == 128) ? (p & 127) : (p & 255);
    float4 v;
    v.x = src[(4 * k4 + 0) * C + c];
    v.y = src[(4 * k4 + 1) * C + c];
    v.z = src[(4 * k4 + 2) * C + c];
    v.w = src[(4 * k4 + 3) * C + c];
    *(float4*)&g_wpack[dstoff + (size_t)p * 4] = v;
}

// ---------------------------------------------------------------------------
// Quad layer accumulate: 4 rows x 1 col over K (k4 = K/4 steps).
// Per k4: 1 LDG.128 (weight quad) + 4 broadcast LDS.128 (acts) + 8 fma2.
// acc[r] = f32x2 (even-k, odd-k) partial sums for row rb+r.
// ---------------------------------------------------------------------------
__device__ __forceinline__ void qlayer(
    ull acc[4], const float* __restrict__ wq, int C, int K4, int col,
    const float* act, int astr, int rb)
{
    acc[0] = acc[1] = acc[2] = acc[3] = 0ULL;
    #pragma unroll 4
    for (int k4 = 0; k4 < K4; ++k4) {
        ulonglong2 w = __ldg((const ulonglong2*)(wq + ((size_t)k4 * C + col) * 4));
        ulonglong2 a0 = *(const ulonglong2*)(act + (rb + 0) * astr + k4 * 4);
        ulonglong2 a1 = *(const ulonglong2*)(act + (rb + 1) * astr + k4 * 4);
        ulonglong2 a2 = *(const ulonglong2*)(act + (rb + 2) * astr + k4 * 4);
        ulonglong2 a3 = *(const ulonglong2*)(act + (rb + 3) * astr + k4 * 4);
        fma2(acc[0], a0.x, w.x); fma2(acc[0], a0.y, w.y);
        fma2(acc[1], a1.x, w.x); fma2(acc[1], a1.y, w.y);
        fma2(acc[2], a2.x, w.x); fma2(acc[2], a2.y, w.y);
        fma2(acc[3], a3.x, w.x); fma2(acc[3], a3.y, w.y);
    }
}

// ---------------------------------------------------------------------------
// Fused encoder: blocks [0,64) = UAV (16 rows), [64,192) = task, 192 = qb.
// 512 threads: j = tid&127 owns col j, rb = (tid>>7)*4 owns 4 rows.
// Weights: packed quads via coalesced LDG.128.  Acts: broadcast LDS.128.
// ---------------------------------------------------------------------------
__global__ __launch_bounds__(512) void enc_fused_kernel(
    const float* __restrict__ uav_feat, const float* __restrict__ task_feat,
    const float* __restrict__ ub0, const float* __restrict__ ub1,
    const float* __restrict__ ub2, const float* __restrict__ tb0,
    const float* __restrict__ tb1, const float* __restrict__ tb2,
    const float* __restrict__ head_q, const float* __restrict__ fw1,
    const float* __restrict__ fb1)
{
    const int bx = blockIdx.x;
    const int tid = threadIdx.x;

    // ---------------- qb block ----------------
    if (bx == 192) {
        int d  = tid & 255;
        int h0 = tid >> 8;            // 0..1
        #pragma unroll
        for (int h = h0; h < H_; h += 2) {
            float acc = fb1[d];
            #pragma unroll 8
            for (int k = 0; k < E_; ++k)
                acc += head_q[h * E_ + k] * fw1[k * HID_ + d];
            g_qb[h * HID_ + d] = acc;
        }
        return;
    }

    const int is_task = (bx >= 64);
    const float* x   = is_task ? task_feat : uav_feat;
    const float* wq0 = g_wpack + (is_task ? QT0_OFF : QW0_OFF);
    const float* wq1 = g_wpack + (is_task ? QT1_OFF : QW1_OFF);
    const float* wq2 = g_wpack + (is_task ? QT2_OFF : QW2_OFF);
    const float* wqf = g_wpack + QF1_OFF + (is_task ? 32 * HID_ * 4 : 0);
    const float* b0  = is_task ? tb0 : ub0;
    const float* b1  = is_task ? tb1 : ub1;
    const float* b2  = is_task ? tb2 : ub2;
    float* out       = is_task ? g_kh : g_qu;
    const int row0   = (is_task ? (bx - 64) : bx) * 16;

    __shared__ float xs[16][IN_DIM_];
    __shared__ float bufA[16][ENC_H_];
    __shared__ float bufB[16][ENC_H_];

    // load 16x32 input tile
    xs[tid >> 5][tid & 31] = x[(size_t)(row0 + (tid >> 5)) * IN_DIM_ + (tid & 31)];
    __syncthreads();

    const int j  = tid & 127;
    const int rb = (tid >> 7) * 4;    // rows rb..rb+3 (warp-uniform)
    ull acc[4];

    // ---- layer 0: K=32 (K4=8), relu ----
    qlayer(acc, wq0, ENC_H_, 8, j, &xs[0][0], IN_DIM_, rb);
    {
        float bv = b0[j];
        #pragma unroll
        for (int r = 0; r < 4; ++r)
            bufA[rb + r][j] = fmaxf(hsum2(acc[r]) + bv, 0.f);
    }
    __syncthreads();

    // ---- layer 1: K=128 (K4=32), relu ----
    qlayer(acc, wq1, ENC_H_, 32, j, &bufA[0][0], ENC_H_, rb);
    {
        float bv = b1[j];
        #pragma unroll
        for (int r = 0; r < 4; ++r)
            bufB[rb + r][j] = fmaxf(hsum2(acc[r]) + bv, 0.f);
    }
    __syncthreads();

    // ---- layer 2: K=128 (K4=32), no relu -> bufA ----
    qlayer(acc, wq2, ENC_H_, 32, j, &bufB[0][0], ENC_H_, rb);
    __syncthreads();   // bufA reads in layer 1 done (already synced); reuse
    {
        float bv = b2[j];
        #pragma unroll
        for (int r = 0; r < 4; ++r)
            bufA[rb + r][j] = hsum2(acc[r]) + bv;
    }
    __syncthreads();

    // ---- projection through fw1 slice: K=128 (K4=32), C=256, 2 passes ----
    #pragma unroll
    for (int p = 0; p < 2; ++p) {
        int col = j + p * 128;
        qlayer(acc, wqf, HID_, 32, col, &bufA[0][0], ENC_H_, rb);
        #pragma unroll
        for (int r = 0; r < 4; ++r)
            out[(size_t)(row0 + rb + r) * HID_ + col] = hsum2(acc[r]);
    }
}

// ---------------------------------------------------------------------------
// Stage E (t-split x d-half): partial[dh][z][u][t] =
//   sum_{d in half} relu(qu[b,u,d]+qb[h,d]+kh[b,t,d]) * fw2[d]
// Grid (tblk:2, dh:2, z:64) = 256 blocks, 512 threads, thread tile 4u x 2t.
// ---------------------------------------------------------------------------
#define DH 128
#define ESTR 132
#define SMEM_E_FLOATS (64 * ESTR + 64 * ESTR + DH)
#define SMEM_E_BYTES  (SMEM_E_FLOATS * 4)

__global__ __launch_bounds__(512, 2) void stageE_k(
    const float* __restrict__ fw2)
{
    extern __shared__ float smem[];
    float* qs   = smem;                        // [64][132]
    float* ks   = smem + 64 * ESTR;            // [64][132]
    float* fw2s = ks + 64 * ESTR;              // [128]

    const int tid = threadIdx.x;
    const int t0  = blockIdx.x * 64;           // 0 or 64
    const int dh  = blockIdx.y;                // 0..1
    const int z   = blockIdx.z;                // b*H + h
    const int b   = z >> 2;
    const int h   = z & 3;
    const int d0  = dh * DH;

    if (tid < DH / 4)
        ((float4*)fw2s)[tid] = ((const float4*)(fw2 + d0))[tid];

    {
        const float4* qb4 = (const float4*)(g_qb + h * HID_ + d0);
        #pragma unroll
        for (int p = 0; p < 4; ++p) {
            int idx = tid + p * 512;
            int u   = idx >> 5;
            int d4  = idx & 31;
            float4 a = ((const float4*)(g_qu + (size_t)(b * U_ + u) * HID_ + d0))[d4];
            float4 qb = qb4[d4];
            a.x += qb.x; a.y += qb.y; a.z += qb.z; a.w += qb.w;
            ((float4*)(qs + u * ESTR))[d4] = a;
        }
    }
    {
        #pragma unroll
        for (int p = 0; p < 4; ++p) {
            int idx = tid + p * 512;
            int t   = idx >> 5;
            int d4  = idx & 31;
            ((float4*)(ks + t * ESTR))[d4] =
                ((const float4*)(g_kh + (size_t)(b * T_ + t0 + t) * HID_ + d0))[d4];
        }
    }
    __syncthreads();

    const int tg = tid & 31;       // t = t0 + tg + 32*jj (jj 0..1)
    const int ug = tid >> 5;       // u = ug*4 + i (warp-uniform)

    ull acc[4][2];
    #pragma unroll
    for (int i = 0; i < 4; ++i) { acc[i][0] = 0ULL; acc[i][1] = 0ULL; }

    const float* qbase = qs + (ug * 4) * ESTR;
    const float* kbase = ks + tg * ESTR;

    #pragma unroll 4
    for (int d4 = 0; d4 < DH / 4; ++d4) {
        ulonglong2 wv = *(const ulonglong2*)(fw2s + d4 * 4);
        ulonglong2 qv[4], kv[2];
        #pragma unroll
        for (int i = 0; i < 4; ++i)
            qv[i] = *(const ulonglong2*)(qbase + i * ESTR + d4 * 4);
        #pragma unroll
        for (int jj = 0; jj < 2; ++jj)
            kv[jj] = *(const ulonglong2*)(kbase + jj * 32 * ESTR + d4 * 4);

        #pragma unroll
        for (int i = 0; i < 4; ++i) {
            #pragma unroll
            for (int jj = 0; jj < 2; ++jj) {
                fma2(acc[i][jj], relu2(add2(qv[i].x, kv[jj].x)), wv.x);
                fma2(acc[i][jj], relu2(add2(qv[i].y, kv[jj].y)), wv.y);
            }
        }
    }

    float* part = g_part[dh] + (size_t)z * U_ * T_;
    #pragma unroll
    for (int i = 0; i < 4; ++i) {
        float* row = part + (ug * 4 + i) * T_ + t0 + tg;
        row[0]  = hsum2(acc[i][0]);
        row[32] = hsum2(acc[i][1]);
    }
}

// ---------------------------------------------------------------------------
// Combine: out = part0 + part1 + fb2 (1 float4 per thread, 512 blocks)
// ---------------------------------------------------------------------------
__global__ __launch_bounds__(256) void combine_kernel(
    float* __restrict__ out, const float* __restrict__ fb2)
{
    const float bias = fb2[0];
    int i = blockIdx.x * 256 + threadIdx.x;      // float4 index, 131072 total
    float4 a = ((const float4*)g_part[0])[i];
    float4 b = ((const float4*)g_part[1])[i];
    float4 r;
    r.x = a.x + b.x + bias;
    r.y = a.y + b.y + bias;
    r.z = a.z + b.z + bias;
    r.w = a.w + b.w + bias;
    ((float4*)out)[i] = r;
}

// ---------------------------------------------------------------------------
extern "C" void kernel_launch(void* const* d_in, const int* in_sizes, int n_in,
                              void* d_out, int out_size)
{
    const float* uav_feat = (const float*)d_in[0];
    const float* task_feat = (const float*)d_in[1];
    const float* uw0 = (const float*)d_in[2];
    const float* ub0 = (const float*)d_in[3];
    const float* uw1 = (const float*)d_in[4];
    const float* ub1 = (const float*)d_in[5];
    const float* uw2 = (const float*)d_in[6];
    const float* ub2 = (const float*)d_in[7];
    const float* tw0 = (const float*)d_in[8];
    const float* tb0 = (const float*)d_in[9];
    const float* tw1 = (const float*)d_in[10];
    const float* tb1 = (const float*)d_in[11];
    const float* tw2 = (const float*)d_in[12];
    const float* tb2 = (const float*)d_in[13];
    const float* head_q = (const float*)d_in[14];
    const float* fw1 = (const float*)d_in[15];
    const float* fb1 = (const float*)d_in[16];
    const float* fw2 = (const float*)d_in[17];
    const float* fb2 = (const float*)d_in[18];
    float* out = (float*)d_out;

    cudaFuncSetAttribute(stageE_k,
                         cudaFuncAttributeMaxDynamicSharedMemorySize,
                         SMEM_E_BYTES);

    // 1) pack weights into k-quad layout
    pack4_kernel<<<136, 256>>>(uw0, uw1, uw2, tw0, tw1, tw2, fw1);

    // 2) encoders + qb (193 blocks x 512 threads, 16 rows/block)
    enc_fused_kernel<<<193, 512>>>(uav_feat, task_feat,
                                   ub0, ub1, ub2, tb0, tb1, tb2,
                                   head_q, fw1, fb1);

    // 3) Stage E over (t:2, d-half:2, z:64)
    dim3 grid(2, 2, B_ * H_);
    stageE_k<<<grid, 512, SMEM_E_BYTES>>>(fw2);

    // 4) combine partials + bias
    combine_kernel<<<512, 256>>>(out, fb2);
}

// round 16
// speedup vs baseline: 1.5444x; 1.5444x over previous
#include <cuda_runtime.h>
#include <cstdint>

// Problem dims (fixed)
#define B_  16
#define U_  64
#define T_  128
#define E_  128
#define HID_ 256
#define H_  4
#define ENC_H_ 128
#define IN_DIM_ 32

typedef unsigned long long ull;

// Scratch (device globals: no allocation allowed)
__device__ float g_qu[B_ * U_ * HID_];    // ue @ fw1[:E]          (1024 x 256)
__device__ float g_kh[B_ * T_ * HID_];    // te @ fw1[E:]          (2048 x 256)
__device__ float g_qb[H_ * HID_];         // head_q @ fw1[:E] + fb1 (4 x 256)
__device__ float g_part[2][B_ * H_ * U_ * T_];  // d-half partial sums

// ---- packed f32x2 helpers (Blackwell) ----
__device__ __forceinline__ ull add2(ull a, ull b) {
    ull r;
    asm("add.rn.f32x2 %0, %1, %2;" : "=l"(r) : "l"(a), "l"(b));
    return r;
}
__device__ __forceinline__ void fma2(ull& acc, ull a, ull b) {
    asm("fma.rn.f32x2 %0, %1, %2, %0;" : "+l"(acc) : "l"(a), "l"(b));
}
__device__ __forceinline__ ull relu2(ull x) {
    float lo, hi;
    asm("mov.b64 {%0,%1}, %2;" : "=f"(lo), "=f"(hi) : "l"(x));
    lo = fmaxf(lo, 0.f);
    hi = fmaxf(hi, 0.f);
    ull r;
    asm("mov.b64 %0, {%1,%2};" : "=l"(r) : "f"(lo), "f"(hi));
    return r;
}
__device__ __forceinline__ float hsum2(ull x) {
    float lo, hi;
    asm("mov.b64 {%0,%1}, %2;" : "=f"(lo), "=f"(hi) : "l"(x));
    return lo + hi;
}

// ---------------------------------------------------------------------------
// Weight load (8 consecutive k, one col): scalar coalesced LDG.32.
// ---------------------------------------------------------------------------
__device__ __forceinline__ void ldw8(float w[8], const float* __restrict__ p, int C)
{
    w[0] = __ldg(p);
    w[1] = __ldg(p + C);
    w[2] = __ldg(p + 2 * C);
    w[3] = __ldg(p + 3 * C);
    w[4] = __ldg(p + 4 * C);
    w[5] = __ldg(p + 5 * C);
    w[6] = __ldg(p + 6 * C);
    w[7] = __ldg(p + 7 * C);
}

// FMA block: 4 rows x 1 col x 8 k using preloaded weights.
__device__ __forceinline__ void fma8(
    float acc[4], const float w[8],
    const float* a0, const float* a1, const float* a2, const float* a3)
{
    float4 x0a = *(const float4*)a0, x0b = *(const float4*)(a0 + 4);
    float4 x1a = *(const float4*)a1, x1b = *(const float4*)(a1 + 4);
    float4 x2a = *(const float4*)a2, x2b = *(const float4*)(a2 + 4);
    float4 x3a = *(const float4*)a3, x3b = *(const float4*)(a3 + 4);
#define ROW8(r, xa, xb) \
    acc[r] = fmaf(xa.x, w[0], acc[r]); acc[r] = fmaf(xa.y, w[1], acc[r]); \
    acc[r] = fmaf(xa.z, w[2], acc[r]); acc[r] = fmaf(xa.w, w[3], acc[r]); \
    acc[r] = fmaf(xb.x, w[4], acc[r]); acc[r] = fmaf(xb.y, w[5], acc[r]); \
    acc[r] = fmaf(xb.z, w[6], acc[r]); acc[r] = fmaf(xb.w, w[7], acc[r]);
    ROW8(0, x0a, x0b)
    ROW8(1, x1a, x1b)
    ROW8(2, x2a, x2b)
    ROW8(3, x3a, x3b)
#undef ROW8
}

// Layer with one-iteration weight prefetch (software pipeline).
// act rows rb..rb+3 (stride astr), col j of W (width C), K k-steps.
__device__ __forceinline__ void pipelayer(
    float acc[4], const float* __restrict__ wcol, int C, int K,
    const float* act, int astr, int rb)
{
    float wbuf[8], wn[8];
    ldw8(wbuf, wcol, C);
    #pragma unroll
    for (int k = 0; k < 128; k += 8) {       // upper bound; guarded by K
        if (k >= K) break;
        if (k + 8 < K) ldw8(wn, wcol + (k + 8) * C, C);
        fma8(acc, wbuf,
             act + (rb + 0) * astr + k, act + (rb + 1) * astr + k,
             act + (rb + 2) * astr + k, act + (rb + 3) * astr + k);
        #pragma unroll
        for (int q = 0; q < 8; ++q) wbuf[q] = wn[q];
    }
}

// ---------------------------------------------------------------------------
// Fused encoder: blocks [0,128) = UAV (8 rows), [128,384) = task, 384 = qb.
// 256 threads: j = tid&127 owns col j, rb = (tid>>7)*4 owns 4 of the 8 rows.
// Weight loads scalar coalesced + 1-iter prefetch; acts broadcast LDS.128.
// ---------------------------------------------------------------------------
__global__ __launch_bounds__(256) void enc_fused_kernel(
    const float* __restrict__ uav_feat, const float* __restrict__ task_feat,
    const float* __restrict__ uw0, const float* __restrict__ ub0,
    const float* __restrict__ uw1, const float* __restrict__ ub1,
    const float* __restrict__ uw2, const float* __restrict__ ub2,
    const float* __restrict__ tw0, const float* __restrict__ tb0,
    const float* __restrict__ tw1, const float* __restrict__ tb1,
    const float* __restrict__ tw2, const float* __restrict__ tb2,
    const float* __restrict__ head_q, const float* __restrict__ fw1,
    const float* __restrict__ fb1)
{
    const int bx = blockIdx.x;
    const int tid = threadIdx.x;

    // ---------------- qb block ----------------
    if (bx == 384) {
        int d = tid;   // 0..255
        #pragma unroll
        for (int h = 0; h < H_; ++h) {
            float acc = fb1[d];
            #pragma unroll 8
            for (int k = 0; k < E_; ++k)
                acc += head_q[h * E_ + k] * fw1[k * HID_ + d];
            g_qb[h * HID_ + d] = acc;
        }
        return;
    }

    const int is_task = (bx >= 128);
    const float* x  = is_task ? task_feat : uav_feat;
    const float* w0 = is_task ? tw0 : uw0;
    const float* b0 = is_task ? tb0 : ub0;
    const float* w1 = is_task ? tw1 : uw1;
    const float* b1 = is_task ? tb1 : ub1;
    const float* w2 = is_task ? tw2 : uw2;
    const float* b2 = is_task ? tb2 : ub2;
    float* out      = is_task ? g_kh : g_qu;
    const int fw1_off = is_task ? E_ : 0;
    const int row0 = (is_task ? (bx - 128) : bx) * 8;

    __shared__ float xs[8][IN_DIM_];
    __shared__ float bufA[8][ENC_H_];
    __shared__ float bufB[8][ENC_H_];

    // load 8x32 input tile (256 threads exactly)
    xs[tid >> 5][tid & 31] = x[(size_t)(row0 + (tid >> 5)) * IN_DIM_ + (tid & 31)];
    __syncthreads();

    const int j  = tid & 127;
    const int rb = (tid >> 7) * 4;    // rows rb..rb+3 (warp-uniform)
    float acc[4];

    // ---- layer 0: 32 -> 128, relu ----
    {
        float bv = b0[j];
        acc[0] = acc[1] = acc[2] = acc[3] = bv;
        pipelayer(acc, w0 + j, ENC_H_, IN_DIM_, &xs[0][0], IN_DIM_, rb);
        #pragma unroll
        for (int r = 0; r < 4; ++r) bufA[rb + r][j] = fmaxf(acc[r], 0.f);
    }
    __syncthreads();

    // ---- layer 1: 128 -> 128, relu ----
    {
        float bv = b1[j];
        acc[0] = acc[1] = acc[2] = acc[3] = bv;
        pipelayer(acc, w1 + j, ENC_H_, ENC_H_, &bufA[0][0], ENC_H_, rb);
        #pragma unroll
        for (int r = 0; r < 4; ++r) bufB[rb + r][j] = fmaxf(acc[r], 0.f);
    }
    __syncthreads();

    // ---- layer 2: 128 -> 128 (no relu) ----
    {
        float bv = b2[j];
        acc[0] = acc[1] = acc[2] = acc[3] = bv;
        pipelayer(acc, w2 + j, ENC_H_, ENC_H_, &bufB[0][0], ENC_H_, rb);
    }
    __syncthreads();   // bufA reads done
    #pragma unroll
    for (int r = 0; r < 4; ++r) bufA[rb + r][j] = acc[r];
    __syncthreads();

    // ---- projection through fw1 slice: 128 -> 256 ----
    const float* wp = fw1 + fw1_off * HID_;
    #pragma unroll
    for (int p = 0; p < 2; ++p) {
        int col = j + p * 128;
        acc[0] = acc[1] = acc[2] = acc[3] = 0.f;
        pipelayer(acc, wp + col, HID_, E_, &bufA[0][0], ENC_H_, rb);
        #pragma unroll
        for (int r = 0; r < 4; ++r)
            out[(size_t)(row0 + rb + r) * HID_ + col] = acc[r];
    }
}

// ---------------------------------------------------------------------------
// Stage E (t-split x d-half): partial[dh][z][u][t] =
//   sum_{d in half} relu(qu[b,u,d]+qb[h,d]+kh[b,t,d]) * fw2[d]
// Grid (tblk:2, dh:2, z:64) = 256 blocks, 512 threads, thread tile 4u x 2t.
// ---------------------------------------------------------------------------
#define DH 128
#define ESTR 132
#define SMEM_E_FLOATS (64 * ESTR + 64 * ESTR + DH)
#define SMEM_E_BYTES  (SMEM_E_FLOATS * 4)

__global__ __launch_bounds__(512, 2) void stageE_k(
    const float* __restrict__ fw2)
{
    extern __shared__ float smem[];
    float* qs   = smem;                        // [64][132]
    float* ks   = smem + 64 * ESTR;            // [64][132]
    float* fw2s = ks + 64 * ESTR;              // [128]

    const int tid = threadIdx.x;
    const int t0  = blockIdx.x * 64;           // 0 or 64
    const int dh  = blockIdx.y;                // 0..1
    const int z   = blockIdx.z;                // b*H + h
    const int b   = z >> 2;
    const int h   = z & 3;
    const int d0  = dh * DH;

    if (tid < DH / 4)
        ((float4*)fw2s)[tid] = ((const float4*)(fw2 + d0))[tid];

    {
        const float4* qb4 = (const float4*)(g_qb + h * HID_ + d0);
        #pragma unroll
        for (int p = 0; p < 4; ++p) {
            int idx = tid + p * 512;
            int u   = idx >> 5;
            int d4  = idx & 31;
            float4 a = ((const float4*)(g_qu + (size_t)(b * U_ + u) * HID_ + d0))[d4];
            float4 qb = qb4[d4];
            a.x += qb.x; a.y += qb.y; a.z += qb.z; a.w += qb.w;
            ((float4*)(qs + u * ESTR))[d4] = a;
        }
    }
    {
        #pragma unroll
        for (int p = 0; p < 4; ++p) {
            int idx = tid + p * 512;
            int t   = idx >> 5;
            int d4  = idx & 31;
            ((float4*)(ks + t * ESTR))[d4] =
                ((const float4*)(g_kh + (size_t)(b * T_ + t0 + t) * HID_ + d0))[d4];
        }
    }
    __syncthreads();

    const int tg = tid & 31;       // t = t0 + tg + 32*jj (jj 0..1)
    const int ug = tid >> 5;       // u = ug*4 + i (warp-uniform)

    ull acc[4][2];
    #pragma unroll
    for (int i = 0; i < 4; ++i) { acc[i][0] = 0ULL; acc[i][1] = 0ULL; }

    const float* qbase = qs + (ug * 4) * ESTR;
    const float* kbase = ks + tg * ESTR;

    #pragma unroll 4
    for (int d4 = 0; d4 < DH / 4; ++d4) {
        ulonglong2 wv = *(const ulonglong2*)(fw2s + d4 * 4);
        ulonglong2 qv[4], kv[2];
        #pragma unroll
        for (int i = 0; i < 4; ++i)
            qv[i] = *(const ulonglong2*)(qbase + i * ESTR + d4 * 4);
        #pragma unroll
        for (int jj = 0; jj < 2; ++jj)
            kv[jj] = *(const ulonglong2*)(kbase + jj * 32 * ESTR + d4 * 4);

        #pragma unroll
        for (int i = 0; i < 4; ++i) {
            #pragma unroll
            for (int jj = 0; jj < 2; ++jj) {
                fma2(acc[i][jj], relu2(add2(qv[i].x, kv[jj].x)), wv.x);
                fma2(acc[i][jj], relu2(add2(qv[i].y, kv[jj].y)), wv.y);
            }
        }
    }

    float* part = g_part[dh] + (size_t)z * U_ * T_;
    #pragma unroll
    for (int i = 0; i < 4; ++i) {
        float* row = part + (ug * 4 + i) * T_ + t0 + tg;
        row[0]  = hsum2(acc[i][0]);
        row[32] = hsum2(acc[i][1]);
    }
}

// ---------------------------------------------------------------------------
// Combine: out = part0 + part1 + fb2 (1 float4 per thread, 512 blocks)
// ---------------------------------------------------------------------------
__global__ __launch_bounds__(256) void combine_kernel(
    float* __restrict__ out, const float* __restrict__ fb2)
{
    const float bias = fb2[0];
    int i = blockIdx.x * 256 + threadIdx.x;      // float4 index, 131072 total
    float4 a = ((const float4*)g_part[0])[i];
    float4 b = ((const float4*)g_part[1])[i];
    float4 r;
    r.x = a.x + b.x + bias;
    r.y = a.y + b.y + bias;
    r.z = a.z + b.z + bias;
    r.w = a.w + b.w + bias;
    ((float4*)out)[i] = r;
}

// ---------------------------------------------------------------------------
extern "C" void kernel_launch(void* const* d_in, const int* in_sizes, int n_in,
                              void* d_out, int out_size)
{
    const float* uav_feat = (const float*)d_in[0];
    const float* task_feat = (const float*)d_in[1];
    const float* uw0 = (const float*)d_in[2];
    const float* ub0 = (const float*)d_in[3];
    const float* uw1 = (const float*)d_in[4];
    const float* ub1 = (const float*)d_in[5];
    const float* uw2 = (const float*)d_in[6];
    const float* ub2 = (const float*)d_in[7];
    const float* tw0 = (const float*)d_in[8];
    const float* tb0 = (const float*)d_in[9];
    const float* tw1 = (const float*)d_in[10];
    const float* tb1 = (const float*)d_in[11];
    const float* tw2 = (const float*)d_in[12];
    const float* tb2 = (const float*)d_in[13];
    const float* head_q = (const float*)d_in[14];
    const float* fw1 = (const float*)d_in[15];
    const float* fb1 = (const float*)d_in[16];
    const float* fw2 = (const float*)d_in[17];
    const float* fb2 = (const float*)d_in[18];
    float* out = (float*)d_out;

    cudaFuncSetAttribute(stageE_k,
                         cudaFuncAttributeMaxDynamicSharedMemorySize,
                         SMEM_E_BYTES);

    // Encoders + qb (385 blocks x 256 threads, 8 rows/block)
    enc_fused_kernel<<<385, 256>>>(uav_feat, task_feat,
                                   uw0, ub0, uw1, ub1, uw2, ub2,
                                   tw0, tb0, tw1, tb1, tw2, tb2,
                                   head_q, fw1, fb1);

    // Stage E over (t:2, d-half:2, z:64)
    dim3 grid(2, 2, B_ * H_);
    stageE_k<<<grid, 512, SMEM_E_BYTES>>>(fw2);

    // Combine partials + bias
    combine_kernel<<<512, 256>>>(out, fb2);
}